// round 8
// baseline (speedup 1.0000x reference)
#include <cuda_runtime.h>
#include <cstdint>

// Problem constants
#define B_DIM   8192
#define IN_DIM  256
#define OUT_DIM 256
#define MV      8

// Tiling: CTA = 64 b (32 bpairs) x 64 i, 128 threads (tx16 x ty8)
// per thread: 4 bpairs x 4 consecutive i; double-buffered smem + reg prefetch
#define MT      64
#define IT      64
#define KJ      8
#define NCH     (IN_DIM / KJ)   // 32
#define XPAD    36
#define NTHR    128

typedef unsigned long long u64;
#define SGN2    0x8000000080000000ull

__device__ __forceinline__ u64 pack2(float lo, float hi) {
    u64 r; asm("mov.b64 %0, {%1, %2};" : "=l"(r) : "f"(lo), "f"(hi)); return r;
}
__device__ __forceinline__ u64 fma2(u64 a, u64 b, u64 c) {
    u64 d; asm("fma.rn.f32x2 %0, %1, %2, %3;" : "=l"(d) : "l"(a), "l"(b), "l"(c)); return d;
}
__device__ __forceinline__ void unpack2(u64 v, float& lo, float& hi) {
    asm("mov.b64 {%0, %1}, %2;" : "=f"(lo), "=f"(hi) : "l"(v));
}

// y[b,i,0] = bias[i,0] + sum_j x0*w0 + x1*w1 + x2*w2
// y[b,i,4] = bias[i,4] + sum_j x1*w2 - x2*w1 + x4*w0
__global__ void __launch_bounds__(NTHR, 3)
ga_mv_kernel(const float* __restrict__ x,
             const float* __restrict__ w,
             const float* __restrict__ bias,
             float* __restrict__ out)
{
    __shared__ u64 Xs[2][KJ][4][XPAD];   // x0,x1,x2,x4 as {b even, b odd}
    __shared__ u64 Ws[2][3][KJ][IT];     // w0,w1,w2 duplicated {w,w}

    const int tid   = threadIdx.x;
    const int tx    = tid & 15;
    const int ty    = tid >> 4;
    const int i0    = tx * 4;          // 4 consecutive i per thread
    const int bp0   = ty * 4;          // 4 bpairs per thread
    const int bBase = blockIdx.x * MT;
    const int iBase = blockIdx.y * IT;

    // staging maps
    const int xj  = tid & 7;           // X: j (cells bp = xbp, xbp+16)
    const int xbp = tid >> 3;
    const int wi  = tid & 63;          // W: i (cells j = wjh + 2t)
    const int wjh = tid >> 6;

    // prefetch registers
    float xA[2][4], xB[2][4];
    float wv[4][3];

    u64 a0[4][4], a4[4][4];
    #pragma unroll
    for (int r = 0; r < 4; r++)
        #pragma unroll
        for (int s = 0; s < 4; s++) { a0[r][s] = 0ull; a4[r][s] = 0ull; }

    auto LOAD = [&](int c) {
        const int j0 = c * KJ;
        #pragma unroll
        for (int t = 0; t < 2; t++) {
            const int bp = xbp + 16 * t;
            const float* ra = x + ((size_t)(bBase + 2 * bp) * IN_DIM + (j0 + xj)) * MV;
            const float* rb = ra + (size_t)IN_DIM * MV;
            float4 a = *(const float4*)ra;
            xA[t][0] = a.x; xA[t][1] = a.y; xA[t][2] = a.z; xA[t][3] = ra[4];
            float4 b = *(const float4*)rb;
            xB[t][0] = b.x; xB[t][1] = b.y; xB[t][2] = b.z; xB[t][3] = rb[4];
        }
        #pragma unroll
        for (int t = 0; t < 4; t++) {
            const float* wr = w + ((size_t)(j0 + wjh + 2 * t) * OUT_DIM + (iBase + wi)) * MV;
            float4 q = *(const float4*)wr;
            wv[t][0] = q.x; wv[t][1] = q.y; wv[t][2] = q.z;
        }
    };

    auto STORE = [&](int buf) {
        #pragma unroll
        for (int t = 0; t < 2; t++) {
            const int bp = xbp + 16 * t;
            Xs[buf][xj][0][bp] = pack2(xA[t][0], xB[t][0]);
            Xs[buf][xj][1][bp] = pack2(xA[t][1], xB[t][1]);
            Xs[buf][xj][2][bp] = pack2(xA[t][2], xB[t][2]);
            Xs[buf][xj][3][bp] = pack2(xA[t][3], xB[t][3]);
        }
        #pragma unroll
        for (int t = 0; t < 4; t++) {
            const int jj = wjh + 2 * t;
            Ws[buf][0][jj][wi] = pack2(wv[t][0], wv[t][0]);
            Ws[buf][1][jj][wi] = pack2(wv[t][1], wv[t][1]);
            Ws[buf][2][jj][wi] = pack2(wv[t][2], wv[t][2]);
        }
    };

    LOAD(0);
    STORE(0);
    __syncthreads();

    for (int c = 0; c < NCH; c++) {
        const int buf = c & 1;
        if (c + 1 < NCH) LOAD(c + 1);     // next-chunk LDG hidden under compute

        #pragma unroll
        for (int j = 0; j < KJ; j++) {
            // X: 4 comps x 4 bpairs as 8 LDS.128
            ulonglong2 v0a = *(const ulonglong2*)&Xs[buf][j][0][bp0];
            ulonglong2 v1a = *(const ulonglong2*)&Xs[buf][j][1][bp0];
            ulonglong2 v2a = *(const ulonglong2*)&Xs[buf][j][2][bp0];
            ulonglong2 v3a = *(const ulonglong2*)&Xs[buf][j][3][bp0];
            ulonglong2 v0b = *(const ulonglong2*)&Xs[buf][j][0][bp0 + 2];
            ulonglong2 v1b = *(const ulonglong2*)&Xs[buf][j][1][bp0 + 2];
            ulonglong2 v2b = *(const ulonglong2*)&Xs[buf][j][2][bp0 + 2];
            ulonglong2 v3b = *(const ulonglong2*)&Xs[buf][j][3][bp0 + 2];

            #pragma unroll
            for (int sh = 0; sh < 2; sh++) {
                // W: 3 comps x 2 consecutive i per LDS.128
                ulonglong2 w0p = *(const ulonglong2*)&Ws[buf][0][j][i0 + 2 * sh];
                ulonglong2 w1p = *(const ulonglong2*)&Ws[buf][1][j][i0 + 2 * sh];
                ulonglong2 w2p = *(const ulonglong2*)&Ws[buf][2][j][i0 + 2 * sh];
                #pragma unroll
                for (int r = 0; r < 4; r++) {
                    const u64 x0  = (r & 2) ? ((r & 1) ? v0b.y : v0b.x) : ((r & 1) ? v0a.y : v0a.x);
                    const u64 x1  = (r & 2) ? ((r & 1) ? v1b.y : v1b.x) : ((r & 1) ? v1a.y : v1a.x);
                    const u64 x2  = (r & 2) ? ((r & 1) ? v2b.y : v2b.x) : ((r & 1) ? v2a.y : v2a.x);
                    const u64 x4  = (r & 2) ? ((r & 1) ? v3b.y : v3b.x) : ((r & 1) ? v3a.y : v3a.x);
                    const u64 x2n = x2 ^ SGN2;   // 2 LOP3 on alu pipe, replaces LDS
                    #pragma unroll
                    for (int s2 = 0; s2 < 2; s2++) {
                        const int s = 2 * sh + s2;
                        const u64 W0 = s2 ? w0p.y : w0p.x;
                        const u64 W1 = s2 ? w1p.y : w1p.x;
                        const u64 W2 = s2 ? w2p.y : w2p.x;
                        a0[r][s] = fma2(x0,  W0, a0[r][s]);
                        a0[r][s] = fma2(x1,  W1, a0[r][s]);
                        a0[r][s] = fma2(x2,  W2, a0[r][s]);
                        a4[r][s] = fma2(x1,  W2, a4[r][s]);
                        a4[r][s] = fma2(x2n, W1, a4[r][s]);
                        a4[r][s] = fma2(x4,  W0, a4[r][s]);
                    }
                }
            }
        }

        if (c + 1 < NCH) STORE(buf ^ 1);
        __syncthreads();
    }

    // ---- epilogue: bias + c0/c4 into slots 0 and 4
    #pragma unroll
    for (int s = 0; s < 4; s++) {
        const int ig = iBase + i0 + s;
        float4 blo = *(const float4*)(bias + (size_t)ig * MV);
        float4 bhi = *(const float4*)(bias + (size_t)ig * MV + 4);
        #pragma unroll
        for (int r = 0; r < 4; r++) {
            float c0e, c0o, c4e, c4o;
            unpack2(a0[r][s], c0e, c0o);
            unpack2(a4[r][s], c4e, c4o);
            const int bE = bBase + 2 * (bp0 + r);

            float4 v0 = blo; v0.x += c0e;
            float4 v1 = bhi; v1.x += c4e;
            float4* o = (float4*)(out + ((size_t)bE * OUT_DIM + ig) * MV);
            o[0] = v0; o[1] = v1;

            v0 = blo; v0.x += c0o;
            v1 = bhi; v1.x += c4o;
            o = (float4*)(out + ((size_t)(bE + 1) * OUT_DIM + ig) * MV);
            o[0] = v0; o[1] = v1;
        }
    }
}

extern "C" void kernel_launch(void* const* d_in, const int* in_sizes, int n_in,
                              void* d_out, int out_size)
{
    const float* x    = (const float*)d_in[0];   // (8192, 256, 8)
    const float* w    = (const float*)d_in[1];   // (256, 256, 8)
    const float* bias = (const float*)d_in[2];   // (256, 8)
    float* out        = (float*)d_out;           // (8192, 256, 8)

    dim3 grid(B_DIM / MT, OUT_DIM / IT);         // (128, 4) = 512 CTAs
    ga_mv_kernel<<<grid, NTHR>>>(x, w, bias, out);
}

// round 9
// speedup vs baseline: 1.1658x; 1.1658x over previous
#include <cuda_runtime.h>
#include <cstdint>

// Problem constants
#define B_DIM   8192
#define IN_DIM  256
#define OUT_DIM 256
#define MV      8

// Tiling: CTA = 64 b (32 bpairs) x 64 i, 128 threads (tx16 x ty8)
// per thread: 4 bpairs x 4 i (i = tx + 16q); double-buffered smem + reg prefetch
#define MT      64
#define IT      64
#define KJ      8
#define NCH     (IN_DIM / KJ)   // 32
#define XPAD    36
#define NTHR    128

typedef unsigned long long u64;
#define SGN2    0x8000000080000000ull

__device__ __forceinline__ u64 pack2(float lo, float hi) {
    u64 r; asm("mov.b64 %0, {%1, %2};" : "=l"(r) : "f"(lo), "f"(hi)); return r;
}
__device__ __forceinline__ u64 fma2(u64 a, u64 b, u64 c) {
    u64 d; asm("fma.rn.f32x2 %0, %1, %2, %3;" : "=l"(d) : "l"(a), "l"(b), "l"(c)); return d;
}
__device__ __forceinline__ void unpack2(u64 v, float& lo, float& hi) {
    asm("mov.b64 {%0, %1}, %2;" : "=f"(lo), "=f"(hi) : "l"(v));
}

// y[b,i,0] = bias[i,0] + sum_j x0*w0 + x1*w1 + x2*w2
// y[b,i,4] = bias[i,4] + sum_j x1*w2 - x2*w1 + x4*w0
__global__ void __launch_bounds__(NTHR, 3)
ga_mv_kernel(const float* __restrict__ x,
             const float* __restrict__ w,
             const float* __restrict__ bias,
             float* __restrict__ out)
{
    __shared__ u64 Xs[2][KJ][4][XPAD];   // x0,x1,x2,x4 as {b even, b odd}
    __shared__ u64 Ws[2][3][KJ][IT];     // w0,w1,w2 duplicated {w,w}

    const int tid   = threadIdx.x;
    const int tx    = tid & 15;        // i = tx + 16q  (broadcast-friendly W LDS.64)
    const int ty    = tid >> 4;
    const int bp0   = ty * 4;          // 4 bpairs per thread
    const int bBase = blockIdx.x * MT;
    const int iBase = blockIdx.y * IT;

    // staging maps
    const int xj  = tid & 7;           // X: j (cells bp = xbp, xbp+16)
    const int xbp = tid >> 3;
    const int wi  = tid & 63;          // W: i (cells j = wjh + 2t)
    const int wjh = tid >> 6;

    // prefetch registers
    float xA[2][4], xB[2][4];
    float wv[4][3];

    u64 a0[4][4], a4[4][4];
    #pragma unroll
    for (int r = 0; r < 4; r++)
        #pragma unroll
        for (int q = 0; q < 4; q++) { a0[r][q] = 0ull; a4[r][q] = 0ull; }

    auto LOAD = [&](int c) {
        const int j0 = c * KJ;
        #pragma unroll
        for (int t = 0; t < 2; t++) {
            const int bp = xbp + 16 * t;
            const float* ra = x + ((size_t)(bBase + 2 * bp) * IN_DIM + (j0 + xj)) * MV;
            const float* rb = ra + (size_t)IN_DIM * MV;
            float4 a = *(const float4*)ra;
            xA[t][0] = a.x; xA[t][1] = a.y; xA[t][2] = a.z; xA[t][3] = ra[4];
            float4 b = *(const float4*)rb;
            xB[t][0] = b.x; xB[t][1] = b.y; xB[t][2] = b.z; xB[t][3] = rb[4];
        }
        #pragma unroll
        for (int t = 0; t < 4; t++) {
            const float* wr = w + ((size_t)(j0 + wjh + 2 * t) * OUT_DIM + (iBase + wi)) * MV;
            float4 q = *(const float4*)wr;
            wv[t][0] = q.x; wv[t][1] = q.y; wv[t][2] = q.z;
        }
    };

    auto STORE = [&](int buf) {
        #pragma unroll
        for (int t = 0; t < 2; t++) {
            const int bp = xbp + 16 * t;
            Xs[buf][xj][0][bp] = pack2(xA[t][0], xB[t][0]);
            Xs[buf][xj][1][bp] = pack2(xA[t][1], xB[t][1]);
            Xs[buf][xj][2][bp] = pack2(xA[t][2], xB[t][2]);
            Xs[buf][xj][3][bp] = pack2(xA[t][3], xB[t][3]);
        }
        #pragma unroll
        for (int t = 0; t < 4; t++) {
            const int jj = wjh + 2 * t;
            Ws[buf][0][jj][wi] = pack2(wv[t][0], wv[t][0]);
            Ws[buf][1][jj][wi] = pack2(wv[t][1], wv[t][1]);
            Ws[buf][2][jj][wi] = pack2(wv[t][2], wv[t][2]);
        }
    };

    LOAD(0);
    STORE(0);
    __syncthreads();

    for (int c = 0; c < NCH; c++) {
        const int buf = c & 1;
        if (c + 1 < NCH) LOAD(c + 1);     // next-chunk LDG hidden under compute

        #pragma unroll
        for (int j = 0; j < KJ; j++) {
            // X: 4 comps x 4 bpairs as 8 LDS.128 (conflict-free: 16 distinct 16B rows)
            ulonglong2 v0a = *(const ulonglong2*)&Xs[buf][j][0][bp0];
            ulonglong2 v1a = *(const ulonglong2*)&Xs[buf][j][1][bp0];
            ulonglong2 v2a = *(const ulonglong2*)&Xs[buf][j][2][bp0];
            ulonglong2 v3a = *(const ulonglong2*)&Xs[buf][j][3][bp0];
            ulonglong2 v0b = *(const ulonglong2*)&Xs[buf][j][0][bp0 + 2];
            ulonglong2 v1b = *(const ulonglong2*)&Xs[buf][j][1][bp0 + 2];
            ulonglong2 v2b = *(const ulonglong2*)&Xs[buf][j][2][bp0 + 2];
            ulonglong2 v3b = *(const ulonglong2*)&Xs[buf][j][3][bp0 + 2];

            #pragma unroll
            for (int qh = 0; qh < 2; qh++) {
                // W: LDS.64 broadcast pattern (16 distinct 8B addrs / warp, conflict-free)
                u64 W0[2], W1[2], W2[2];
                #pragma unroll
                for (int s = 0; s < 2; s++) {
                    const int q = 2 * qh + s;
                    W0[s] = Ws[buf][0][j][tx + 16 * q];
                    W1[s] = Ws[buf][1][j][tx + 16 * q];
                    W2[s] = Ws[buf][2][j][tx + 16 * q];
                }
                #pragma unroll
                for (int r = 0; r < 4; r++) {
                    const u64 x0  = (r & 2) ? ((r & 1) ? v0b.y : v0b.x) : ((r & 1) ? v0a.y : v0a.x);
                    const u64 x1  = (r & 2) ? ((r & 1) ? v1b.y : v1b.x) : ((r & 1) ? v1a.y : v1a.x);
                    const u64 x2  = (r & 2) ? ((r & 1) ? v2b.y : v2b.x) : ((r & 1) ? v2a.y : v2a.x);
                    const u64 x4  = (r & 2) ? ((r & 1) ? v3b.y : v3b.x) : ((r & 1) ? v3a.y : v3a.x);
                    const u64 x2n = x2 ^ SGN2;     // alu-pipe sign flip, replaces 5th comp LDS
                    #pragma unroll
                    for (int s = 0; s < 2; s++) {
                        const int q = 2 * qh + s;
                        a0[r][q] = fma2(x0,  W0[s], a0[r][q]);
                        a0[r][q] = fma2(x1,  W1[s], a0[r][q]);
                        a0[r][q] = fma2(x2,  W2[s], a0[r][q]);
                        a4[r][q] = fma2(x1,  W2[s], a4[r][q]);
                        a4[r][q] = fma2(x2n, W1[s], a4[r][q]);
                        a4[r][q] = fma2(x4,  W0[s], a4[r][q]);
                    }
                }
            }
        }

        if (c + 1 < NCH) STORE(buf ^ 1);
        __syncthreads();
    }

    // ---- epilogue: bias + c0/c4 into slots 0 and 4
    #pragma unroll
    for (int q = 0; q < 4; q++) {
        const int ig = iBase + tx + 16 * q;
        float4 blo = *(const float4*)(bias + (size_t)ig * MV);
        float4 bhi = *(const float4*)(bias + (size_t)ig * MV + 4);
        #pragma unroll
        for (int r = 0; r < 4; r++) {
            float c0e, c0o, c4e, c4o;
            unpack2(a0[r][q], c0e, c0o);
            unpack2(a4[r][q], c4e, c4o);
            const int bE = bBase + 2 * (bp0 + r);

            float4 v0 = blo; v0.x += c0e;
            float4 v1 = bhi; v1.x += c4e;
            float4* o = (float4*)(out + ((size_t)bE * OUT_DIM + ig) * MV);
            o[0] = v0; o[1] = v1;

            v0 = blo; v0.x += c0o;
            v1 = bhi; v1.x += c4o;
            o = (float4*)(out + ((size_t)(bE + 1) * OUT_DIM + ig) * MV);
            o[0] = v0; o[1] = v1;
        }
    }
}

extern "C" void kernel_launch(void* const* d_in, const int* in_sizes, int n_in,
                              void* d_out, int out_size)
{
    const float* x    = (const float*)d_in[0];   // (8192, 256, 8)
    const float* w    = (const float*)d_in[1];   // (256, 256, 8)
    const float* bias = (const float*)d_in[2];   // (256, 8)
    float* out        = (float*)d_out;           // (8192, 256, 8)

    dim3 grid(B_DIM / MT, OUT_DIM / IT);         // (128, 4) = 512 CTAs
    ga_mv_kernel<<<grid, NTHR>>>(x, w, bias, out);
}

// round 10
// speedup vs baseline: 1.2733x; 1.0921x over previous
#include <cuda_runtime.h>
#include <cstdint>

// Problem constants
#define B_DIM   8192
#define IN_DIM  256
#define OUT_DIM 256
#define MV      8

// Tiling: CTA = 64 b (32 bpairs) x 64 i, 128 threads (tx16 x ty8)
// per thread: 4 bpairs x 4 i (i = tx + 16q)
// 2 CTAs/SM, big register budget: chunk-level LDG prefetch (as R7)
// + j-level LDS software pipeline (new)
#define MT      64
#define IT      64
#define KJ      8
#define NCH     (IN_DIM / KJ)   // 32
#define XPAD    36
#define NTHR    128

typedef unsigned long long u64;

__device__ __forceinline__ u64 pack2(float lo, float hi) {
    u64 r; asm("mov.b64 %0, {%1, %2};" : "=l"(r) : "f"(lo), "f"(hi)); return r;
}
__device__ __forceinline__ u64 fma2(u64 a, u64 b, u64 c) {
    u64 d; asm("fma.rn.f32x2 %0, %1, %2, %3;" : "=l"(d) : "l"(a), "l"(b), "l"(c)); return d;
}
__device__ __forceinline__ void unpack2(u64 v, float& lo, float& hi) {
    asm("mov.b64 {%0, %1}, %2;" : "=f"(lo), "=f"(hi) : "l"(v));
}

// y[b,i,0] = bias[i,0] + sum_j x0*w0 + x1*w1 + x2*w2
// y[b,i,4] = bias[i,4] + sum_j x1*w2 - x2*w1 + x4*w0
__global__ void __launch_bounds__(NTHR, 2)
ga_mv_kernel(const float* __restrict__ x,
             const float* __restrict__ w,
             const float* __restrict__ bias,
             float* __restrict__ out)
{
    __shared__ u64 Xs[2][KJ][5][XPAD];   // x0,x1,x2,x4,-x2 as {b even, b odd}
    __shared__ u64 Ws[2][3][KJ][IT];     // w0,w1,w2 duplicated {w,w}

    const int tid   = threadIdx.x;
    const int tx    = tid & 15;        // i = tx + 16q (broadcast-friendly W LDS.64)
    const int ty    = tid >> 4;
    const int bp0   = ty * 4;          // 4 bpairs per thread
    const int bBase = blockIdx.x * MT;
    const int iBase = blockIdx.y * IT;

    // staging maps
    const int xj  = tid & 7;           // X: j (cells bp = xbp, xbp+16)
    const int xbp = tid >> 3;
    const int wi  = tid & 63;          // W: i (cells j = wjh + 2t)
    const int wjh = tid >> 6;

    // chunk-level LDG prefetch registers
    float xA[2][4], xB[2][4];
    float wv[4][3];

    // j-level LDS pipeline register sets: [set][comp][half]
    ulonglong2 xv[2][5][2];

    u64 a0[4][4], a4[4][4];
    #pragma unroll
    for (int r = 0; r < 4; r++)
        #pragma unroll
        for (int q = 0; q < 4; q++) { a0[r][q] = 0ull; a4[r][q] = 0ull; }

    auto LOAD = [&](int c) {
        const int j0 = c * KJ;
        #pragma unroll
        for (int t = 0; t < 2; t++) {
            const int bp = xbp + 16 * t;
            const float* ra = x + ((size_t)(bBase + 2 * bp) * IN_DIM + (j0 + xj)) * MV;
            const float* rb = ra + (size_t)IN_DIM * MV;
            float4 a = *(const float4*)ra;
            xA[t][0] = a.x; xA[t][1] = a.y; xA[t][2] = a.z; xA[t][3] = ra[4];
            float4 b = *(const float4*)rb;
            xB[t][0] = b.x; xB[t][1] = b.y; xB[t][2] = b.z; xB[t][3] = rb[4];
        }
        #pragma unroll
        for (int t = 0; t < 4; t++) {
            const float* wr = w + ((size_t)(j0 + wjh + 2 * t) * OUT_DIM + (iBase + wi)) * MV;
            float4 q = *(const float4*)wr;
            wv[t][0] = q.x; wv[t][1] = q.y; wv[t][2] = q.z;
        }
    };

    auto STORE = [&](int buf) {
        #pragma unroll
        for (int t = 0; t < 2; t++) {
            const int bp = xbp + 16 * t;
            Xs[buf][xj][0][bp] = pack2(xA[t][0],  xB[t][0]);
            Xs[buf][xj][1][bp] = pack2(xA[t][1],  xB[t][1]);
            Xs[buf][xj][2][bp] = pack2(xA[t][2],  xB[t][2]);
            Xs[buf][xj][3][bp] = pack2(xA[t][3],  xB[t][3]);
            Xs[buf][xj][4][bp] = pack2(-xA[t][2], -xB[t][2]);
        }
        #pragma unroll
        for (int t = 0; t < 4; t++) {
            const int jj = wjh + 2 * t;
            Ws[buf][0][jj][wi] = pack2(wv[t][0], wv[t][0]);
            Ws[buf][1][jj][wi] = pack2(wv[t][1], wv[t][1]);
            Ws[buf][2][jj][wi] = pack2(wv[t][2], wv[t][2]);
        }
    };

    auto LDX = [&](int buf, int j, int set) {
        #pragma unroll
        for (int cmp = 0; cmp < 5; cmp++) {
            xv[set][cmp][0] = *(const ulonglong2*)&Xs[buf][j][cmp][bp0];
            xv[set][cmp][1] = *(const ulonglong2*)&Xs[buf][j][cmp][bp0 + 2];
        }
    };

    LOAD(0);
    STORE(0);
    __syncthreads();

    for (int c = 0; c < NCH; c++) {
        const int buf = c & 1;
        if (c + 1 < NCH) LOAD(c + 1);     // next-chunk LDG, hidden under compute

        LDX(buf, 0, 0);                   // prime j-pipeline

        #pragma unroll
        for (int j = 0; j < KJ; j++) {
            const int set = j & 1;
            if (j + 1 < KJ) LDX(buf, j + 1, set ^ 1);   // prefetch next j's X

            #pragma unroll
            for (int qh = 0; qh < 2; qh++) {
                u64 W0[2], W1[2], W2[2];
                #pragma unroll
                for (int s = 0; s < 2; s++) {
                    const int q = 2 * qh + s;
                    W0[s] = Ws[buf][0][j][tx + 16 * q];
                    W1[s] = Ws[buf][1][j][tx + 16 * q];
                    W2[s] = Ws[buf][2][j][tx + 16 * q];
                }
                #pragma unroll
                for (int r = 0; r < 4; r++) {
                    const int h  = r >> 1;
                    const int rr = r & 1;
                    const u64 x0  = rr ? xv[set][0][h].y : xv[set][0][h].x;
                    const u64 x1  = rr ? xv[set][1][h].y : xv[set][1][h].x;
                    const u64 x2  = rr ? xv[set][2][h].y : xv[set][2][h].x;
                    const u64 x4  = rr ? xv[set][3][h].y : xv[set][3][h].x;
                    const u64 x2n = rr ? xv[set][4][h].y : xv[set][4][h].x;
                    #pragma unroll
                    for (int s = 0; s < 2; s++) {
                        const int q = 2 * qh + s;
                        a0[r][q] = fma2(x0,  W0[s], a0[r][q]);
                        a0[r][q] = fma2(x1,  W1[s], a0[r][q]);
                        a0[r][q] = fma2(x2,  W2[s], a0[r][q]);
                        a4[r][q] = fma2(x1,  W2[s], a4[r][q]);
                        a4[r][q] = fma2(x2n, W1[s], a4[r][q]);
                        a4[r][q] = fma2(x4,  W0[s], a4[r][q]);
                    }
                }
            }
        }

        if (c + 1 < NCH) STORE(buf ^ 1);
        __syncthreads();
    }

    // ---- epilogue: bias + c0/c4 into slots 0 and 4
    #pragma unroll
    for (int q = 0; q < 4; q++) {
        const int ig = iBase + tx + 16 * q;
        float4 blo = *(const float4*)(bias + (size_t)ig * MV);
        float4 bhi = *(const float4*)(bias + (size_t)ig * MV + 4);
        #pragma unroll
        for (int r = 0; r < 4; r++) {
            float c0e, c0o, c4e, c4o;
            unpack2(a0[r][q], c0e, c0o);
            unpack2(a4[r][q], c4e, c4o);
            const int bE = bBase + 2 * (bp0 + r);

            float4 v0 = blo; v0.x += c0e;
            float4 v1 = bhi; v1.x += c4e;
            float4* o = (float4*)(out + ((size_t)bE * OUT_DIM + ig) * MV);
            o[0] = v0; o[1] = v1;

            v0 = blo; v0.x += c0o;
            v1 = bhi; v1.x += c4o;
            o = (float4*)(out + ((size_t)(bE + 1) * OUT_DIM + ig) * MV);
            o[0] = v0; o[1] = v1;
        }
    }
}

extern "C" void kernel_launch(void* const* d_in, const int* in_sizes, int n_in,
                              void* d_out, int out_size)
{
    const float* x    = (const float*)d_in[0];   // (8192, 256, 8)
    const float* w    = (const float*)d_in[1];   // (256, 256, 8)
    const float* bias = (const float*)d_in[2];   // (256, 8)
    float* out        = (float*)d_out;           // (8192, 256, 8)

    dim3 grid(B_DIM / MT, OUT_DIM / IT);         // (128, 4) = 512 CTAs
    ga_mv_kernel<<<grid, NTHR>>>(x, w, bias, out);
}